// round 9
// baseline (speedup 1.0000x reference)
#include <cuda_runtime.h>
#include <cstdint>

// Problem constants
#define Bn 32
#define Cn 64
#define Hn 112
#define Wn 112
static constexpr int HW    = Hn * Wn;        // 12544
static constexpr int BHW   = Bn * HW;        // 401408
static constexpr int TOTAL = Bn * Cn * HW;   // 25690112
static constexpr float ALPHA = 0.25f;

// Padded channel-last int8 activations: one pixel = 64 contiguous int8 (+/-1),
// zero halo rows/cols by construction (written only at interior positions;
// .bss zeros elsewhere). Linear-offset im2col over this layout is exact.
static constexpr int PW            = 114;      // 112 + 2 halo
static constexpr int PHW           = PW * PW;  // 12996
static constexpr int TILE_M        = 256;      // padded positions per CTA
static constexpr int TILES_PER_IMG = 51;       // 51*256 = 13056 >= 12996
static constexpr int IMG_STRIDE    = 13184;    // >= 13056 + 115 tail slack
static constexpr int GUARD         = 128;      // front guard rows (>=115)
static constexpr int NCTA          = Bn * TILES_PER_IMG;   // 1632

__device__ __align__(16) signed char g_act1[((size_t)GUARD + (size_t)Bn * IMG_STRIDE) * 64];
__device__ __align__(16) signed char g_act2[((size_t)GUARD + (size_t)Bn * IMG_STRIDE) * 64];
__device__ float g_out1[TOTAL];
__device__ __align__(16) signed char g_wb[2][9][64][64];   // +/-1 weights [set][tap][oc][ic]

struct CParams {
    float4 par[2][Cn];   // {ALPHA*scale, bA, aP, bB}
    float  k1[Cn];       // b21
};
__device__   CParams g_cp;
__constant__ CParams c_cp;

// SMEM layout (dynamic):
//   A: 487 rows x 80 B (64 B data + 16 pad -> conflict-free ldmatrix)  = 38960
//   B: 9 taps x 64 oc x 80 B                                           = 46080
//   E: 8 warps x 32 px x 69 words (transpose buffer, stride 69 -> CF)  = 70656
static constexpr int SM_A  = 0;
static constexpr int SM_B  = 38960;
static constexpr int SM_E  = 85040;
static constexpr int SMEM_DYN = 155696;

__device__ __forceinline__ uint32_t smem_u32(const void* p) {
    uint32_t a;
    asm("{ .reg .u64 t; cvta.to.shared.u64 t, %1; cvt.u32.u64 %0, t; }"
        : "=r"(a) : "l"(p));
    return a;
}

#define LDSM_X4(r, addr) \
    asm volatile("ldmatrix.sync.aligned.m8n8.x4.shared.b16 {%0,%1,%2,%3}, [%4];" \
        : "=r"((r)[0]), "=r"((r)[1]), "=r"((r)[2]), "=r"((r)[3]) : "r"(addr))

#define MMA_S8(c, a, b0, b1) \
    asm volatile("mma.sync.aligned.m16n8k32.row.col.s32.s8.s8.s32 " \
        "{%0,%1,%2,%3}, {%4,%5,%6,%7}, {%8,%9}, {%0,%1,%2,%3};" \
        : "+r"((c)[0]), "+r"((c)[1]), "+r"((c)[2]), "+r"((c)[3]) \
        : "r"((a)[0]), "r"((a)[1]), "r"((a)[2]), "r"((a)[3]), "r"(b0), "r"(b1))

// ============================ prep kernel ===================================
__global__ void prep_weights(const float* __restrict__ w3,
                             const float* __restrict__ wpw,
                             const float* __restrict__ b12,
                             const float* __restrict__ a1,
                             const float* __restrict__ b13,
                             const float* __restrict__ b22,
                             const float* __restrict__ a2,
                             const float* __restrict__ b23,
                             const float* __restrict__ b21)
{
    int t = threadIdx.x;            // 0..127
    int set = t >> 6;               // 0 = w3, 1 = w_pw
    int oc  = t & 63;
    const float* w = set ? wpw : w3;
    float s = 0.f;
    #pragma unroll
    for (int tap = 0; tap < 9; tap++) {
        for (int ic = 0; ic < 64; ic++) {
            float v = w[(oc * 64 + ic) * 9 + tap];
            s += fabsf(v);
            g_wb[set][tap][oc][ic] = (v >= 0.f) ? (signed char)1 : (signed char)-1;
        }
    }
    float scale = s * (1.f / 576.f);
    if (set == 0) {
        g_cp.par[0][oc] = make_float4(ALPHA * scale, b12[oc], a1[oc], b13[oc]);
        g_cp.k1[oc] = b21[oc];
    } else {
        g_cp.par[1][oc] = make_float4(ALPHA * scale, b22[oc], a2[oc], b23[oc]);
    }
}

// ============================ pack1 kernel ==================================
// bin_act(x + b11) -> int8 +/-1 into padded channel-last layout (4 px/thread).
__global__ void pack1_kernel(const float* __restrict__ x,
                             const float* __restrict__ b11)
{
    __shared__ float sb[64];
    if (threadIdx.x < 64) sb[threadIdx.x] = b11[threadIdx.x];
    __syncthreads();

    int t = blockIdx.x * blockDim.x + threadIdx.x;
    if (t >= BHW / 4) return;
    int b  = t / (HW / 4);
    int hw = (t - b * (HW / 4)) * 4;
    int y  = hw / Wn, xx = hw - y * Wn;   // xx..xx+3 stay within the row (112%4==0)
    const float4* xp = (const float4*)(x + (size_t)b * Cn * HW + hw);

    const size_t pp = (size_t)(y + 1) * PW + (xx + 1);
    signed char* dst = g_act1 + ((size_t)GUARD + (size_t)b * IMG_STRIDE + pp) * 64;

    // 4 channel-groups of 16: build 4x4 words, store one uint4 per pixel row
    #pragma unroll
    for (int g = 0; g < 4; g++) {
        uint32_t w0[4], w1[4], w2[4], w3v[4];
        #pragma unroll
        for (int cc = 0; cc < 16; cc++) {
            int c = g * 16 + cc;
            float4 v = __ldg(&xp[c * (HW / 4)]);
            float bc = sb[c];
            uint32_t sh = (cc & 3) * 8;
            uint32_t b0 = ((v.x + bc >= 0.f) ? 0x01u : 0xFFu) << sh;
            uint32_t b1 = ((v.y + bc >= 0.f) ? 0x01u : 0xFFu) << sh;
            uint32_t b2 = ((v.z + bc >= 0.f) ? 0x01u : 0xFFu) << sh;
            uint32_t b3 = ((v.w + bc >= 0.f) ? 0x01u : 0xFFu) << sh;
            int q = cc >> 2;
            if ((cc & 3) == 0) { w0[q] = b0; w1[q] = b1; w2[q] = b2; w3v[q] = b3; }
            else               { w0[q] |= b0; w1[q] |= b1; w2[q] |= b2; w3v[q] |= b3; }
        }
        *(uint4*)(dst + 0 * 64 + g * 16) = make_uint4(w0[0], w0[1], w0[2], w0[3]);
        *(uint4*)(dst + 1 * 64 + g * 16) = make_uint4(w1[0], w1[1], w1[2], w1[3]);
        *(uint4*)(dst + 2 * 64 + g * 16) = make_uint4(w2[0], w2[1], w2[2], w2[3]);
        *(uint4*)(dst + 3 * 64 + g * 16) = make_uint4(w3v[0], w3v[1], w3v[2], w3v[3]);
    }
}

// ============================ conv kernel (IMMA) ============================
// CTA = 256 threads = 8 warps; warp w covers padded positions [w*32, w*32+32)
// of the CTA's 256-position tile. Warp tile: m32 x n64, K = 9 taps x 64 ic,
// k-chunks of 32 -> 18 chunks x (2 A-ldsm + 4 B-ldsm + 16 mma).
template <int STAGE>
__global__ void __launch_bounds__(256)
conv_mma(const float* __restrict__ resid, float* __restrict__ outp)
{
    extern __shared__ __align__(16) char sm[];
    const int tid = threadIdx.x, wid = tid >> 5, lane = tid & 31;
    const int cta = blockIdx.x;
    const int img = cta / TILES_PER_IMG;
    const int tt  = cta - img * TILES_PER_IMG;
    const int P0  = tt * TILE_M;
    const long long grow0 = (long long)GUARD + (long long)img * IMG_STRIDE + P0 - 115;

    const signed char* act = (STAGE == 1) ? g_act1 : g_act2;

    // Stage B weights: [tap][oc] rows of 64 B at stride 80
    {
        const uint4* src = (const uint4*)&g_wb[STAGE - 1][0][0][0];
        for (int i = tid; i < 9 * 64 * 4; i += 256) {
            int tap = i >> 8, r = i & 255, oc = r >> 2, ic4 = r & 3;
            *(uint4*)(sm + SM_B + tap * 5120 + oc * 80 + ic4 * 16) = src[i];
        }
    }
    // Stage A activations: 487 rows (tile + halo) of 64 B at stride 80
    {
        const uint4* src = (const uint4*)(act + grow0 * 64);
        for (int i = tid; i < 487 * 4; i += 256) {
            int r = i >> 2, c = i & 3;
            *(uint4*)(sm + SM_A + r * 80 + c * 16) = src[i];
        }
    }
    __syncthreads();

    const uint32_t smA = smem_u32(sm + SM_A);
    const uint32_t smB = smem_u32(sm + SM_B);
    const int wbase = wid * 32;

    // ldmatrix lane address components (x4: lanes 0-7 tile0, 8-15 t1, 16-23 t2, 24-31 t3)
    const int subr = ((lane >> 3) & 1) * 8 + (lane & 7);  // row within 16-row block
    const int k16  = (lane >> 4) & 1;                     // k 16-byte half select
    const uint32_t aBase = smA + (uint32_t)(wbase + 115 + subr) * 80 + k16 * 16;
    const uint32_t bBase = smB + (uint32_t)subr * 80 + k16 * 16;

    int c[2][8][4];
    #pragma unroll
    for (int mt = 0; mt < 2; mt++)
        #pragma unroll
        for (int n = 0; n < 8; n++)
            #pragma unroll
            for (int k = 0; k < 4; k++) c[mt][n][k] = 0;

    const int TAPOFF[9] = {-115, -114, -113, -1, 0, 1, 113, 114, 115};

    #pragma unroll
    for (int kc = 0; kc < 18; kc++) {
        const int tap = kc >> 1, half = kc & 1;
        uint32_t a[2][4];
        #pragma unroll
        for (int mt = 0; mt < 2; mt++) {
            uint32_t addr = aBase + (uint32_t)((mt * 16 + TAPOFF[tap]) * 80 + half * 32);
            LDSM_X4(a[mt], addr);
        }
        #pragma unroll
        for (int q = 0; q < 4; q++) {
            uint32_t b[4];
            uint32_t addr = bBase + (uint32_t)(tap * 5120 + q * 1280 + half * 32);
            LDSM_X4(b, addr);
            #pragma unroll
            for (int mt = 0; mt < 2; mt++) {
                MMA_S8(c[mt][2 * q],     a[mt], b[0], b[2]);
                MMA_S8(c[mt][2 * q + 1], a[mt], b[1], b[3]);
            }
        }
    }

    // Transpose accumulators through SMEM: E[px 0..31][oc 0..63], stride 69
    int* E = (int*)(sm + SM_E) + wid * (32 * 69);
    #pragma unroll
    for (int mt = 0; mt < 2; mt++)
        #pragma unroll
        for (int n = 0; n < 8; n++) {
            int base = (mt * 16 + (lane >> 2)) * 69 + n * 8 + (lane & 3) * 2;
            E[base]              = c[mt][n][0];
            E[base + 1]          = c[mt][n][1];
            E[base + 8 * 69]     = c[mt][n][2];
            E[base + 8 * 69 + 1] = c[mt][n][3];
        }
    __syncwarp();

    // Pass 2: lane = pixel (coalesced resid/output per oc-plane)
    const int pp = P0 + wbase + lane;
    const int ypad = pp / PW, xpad = pp - ypad * PW;
    const bool interior = (ypad >= 1) & (ypad <= Hn) & (xpad >= 1) & (xpad <= Wn);
    if (interior) {
        const int hw = (ypad - 1) * Wn + (xpad - 1);
        const float* rp = resid + (size_t)img * Cn * HW + hw;
        float*       op = outp  + (size_t)img * Cn * HW + hw;
        const int* Er = E + lane * 69;

        uint32_t bits[16];
        #pragma unroll 1
        for (int oc0 = 0; oc0 < 64; oc0 += 8) {
            float r[8];
            #pragma unroll
            for (int j = 0; j < 8; j++) r[j] = rp[(oc0 + j) * HW];
            #pragma unroll
            for (int j = 0; j < 8; j++) {
                const int oc = oc0 + j;
                int d = Er[oc];
                float4 P = c_cp.par[STAGE - 1][oc];
                float o = fmaf(P.x, (float)d, r[j]);
                float u = o + P.y;
                o = (u >= 0.f ? u : P.z * u) + P.w;
                op[oc * HW] = o;
                if (STAGE == 1) {
                    uint32_t by = ((o + c_cp.k1[oc] >= 0.f) ? 0x01u : 0xFFu) << ((oc & 3) * 8);
                    if ((oc & 3) == 0) bits[oc >> 2] = by; else bits[oc >> 2] |= by;
                }
            }
        }
        if (STAGE == 1) {
            uint4* dst = (uint4*)(g_act2 +
                ((size_t)GUARD + (size_t)img * IMG_STRIDE + pp) * 64);
            dst[0] = make_uint4(bits[0],  bits[1],  bits[2],  bits[3]);
            dst[1] = make_uint4(bits[4],  bits[5],  bits[6],  bits[7]);
            dst[2] = make_uint4(bits[8],  bits[9],  bits[10], bits[11]);
            dst[3] = make_uint4(bits[12], bits[13], bits[14], bits[15]);
        }
    }
}

// ---------------------------------------------------------------------------
extern "C" void kernel_launch(void* const* d_in, const int* in_sizes, int n_in,
                              void* d_out, int out_size)
{
    const float* x   = (const float*)d_in[0];
    const float* w3  = (const float*)d_in[1];
    const float* wpw = (const float*)d_in[2];
    const float* b11 = (const float*)d_in[3];
    const float* b12 = (const float*)d_in[4];
    const float* b13 = (const float*)d_in[5];
    const float* b21 = (const float*)d_in[6];
    const float* b22 = (const float*)d_in[7];
    const float* b23 = (const float*)d_in[8];
    const float* a1  = (const float*)d_in[9];
    const float* a2  = (const float*)d_in[10];
    float* out = (float*)d_out;

    void *p_stage = nullptr, *p_const = nullptr, *p_out1 = nullptr;
    cudaGetSymbolAddress(&p_stage, g_cp);
    cudaGetSymbolAddress(&p_const, c_cp);
    cudaGetSymbolAddress(&p_out1, g_out1);

    cudaFuncSetAttribute(conv_mma<1>, cudaFuncAttributeMaxDynamicSharedMemorySize, SMEM_DYN);
    cudaFuncSetAttribute(conv_mma<2>, cudaFuncAttributeMaxDynamicSharedMemorySize, SMEM_DYN);

    prep_weights<<<1, 128>>>(w3, wpw, b12, a1, b13, b22, a2, b23, b21);
    cudaMemcpyAsync(p_const, p_stage, sizeof(CParams), cudaMemcpyDeviceToDevice);
    pack1_kernel<<<(BHW / 4 + 255) / 256, 256>>>(x, b11);
    conv_mma<1><<<NCTA, 256, SMEM_DYN>>>(x, (float*)p_out1);
    conv_mma<2><<<NCTA, 256, SMEM_DYN>>>((const float*)p_out1, out);
}

// round 10
// speedup vs baseline: 3.6589x; 3.6589x over previous
#include <cuda_runtime.h>
#include <cstdint>

// Problem constants
#define Bn 32
#define Cn 64
#define Hn 112
#define Wn 112
static constexpr int HW    = Hn * Wn;        // 12544
static constexpr int BHW   = Bn * HW;        // 401408
static constexpr int TOTAL = Bn * Cn * HW;   // 25690112
static constexpr float ALPHA = 0.25f;

// Interior / boundary enumeration
static constexpr int NI_IMG  = 110 * 110;    // 12100 interior px / image
static constexpr int NI_TOT  = Bn * NI_IMG;  // 387200
static constexpr int NI_CTAS = (NI_TOT + 255) / 256;   // 1513
static constexpr int NB_IMG  = 444;          // boundary ring px / image
static constexpr int NB_TOT  = Bn * NB_IMG;  // 14208
static constexpr int NB_CTAS = (NB_TOT + 255) / 256;   // 56

// Scratch (no cudaMalloc allowed)
__device__ unsigned long long g_bits1[BHW];
__device__ unsigned long long g_bits2[BHW];
__device__ float g_out1[TOTAL];              // ~103 MB .bss

struct CParams {
    unsigned long long w[2][Cn][10];   // packed sign words (tap 0..8) + pad
    unsigned long long tab[2][Cn];     // byte-packed boundary popc corrections
    float4 par[2][Cn];                 // {ALPHA*scale, bA, aP, bB}
    float  k1[Cn];                     // b21 (stage-1 repack bias)
};
__device__   CParams g_cb;   // staging (written by prep kernel)
__constant__ CParams c_cb;   // read by conv kernels (LDCU/uniform path)

// ---------------------------------------------------------------------------
// K0: PARALLEL weight prep. grid = 128 blocks (set*64+oc), block = 64 (ic).
// Ballot-based sign packing; smem reduction for mean|w|.
// ---------------------------------------------------------------------------
__global__ void prep_weights(const float* __restrict__ w3,
                             const float* __restrict__ wpw,
                             const float* __restrict__ b12,
                             const float* __restrict__ a1,
                             const float* __restrict__ b13,
                             const float* __restrict__ b22,
                             const float* __restrict__ a2,
                             const float* __restrict__ b23,
                             const float* __restrict__ b21)
{
    const int set = blockIdx.x >> 6;
    const int oc  = blockIdx.x & 63;
    const int ic  = threadIdx.x;          // 0..63
    const int lane = ic & 31, wrp = ic >> 5;
    const float* w = set ? wpw : w3;

    __shared__ float ssum[64];
    __shared__ unsigned sb[2][9];

    float s = 0.f;
    unsigned mybits = 0;
    #pragma unroll
    for (int tap = 0; tap < 9; tap++) {
        float v = w[(oc * 64 + ic) * 9 + tap];
        s += fabsf(v);
        mybits |= (v >= 0.f) ? (1u << tap) : 0u;
    }
    #pragma unroll
    for (int tap = 0; tap < 9; tap++) {
        unsigned bal = __ballot_sync(0xFFFFFFFFu, (mybits >> tap) & 1u);
        if (lane == 0) sb[wrp][tap] = bal;
    }
    ssum[ic] = s;
    __syncthreads();

    if (ic == 0) {
        float t = 0.f;
        #pragma unroll
        for (int i = 0; i < 64; i++) t += ssum[i];
        float scale = t * (1.f / 576.f);

        unsigned long long wd[9], pc[9];
        #pragma unroll
        for (int tap = 0; tap < 9; tap++) {
            wd[tap] = (unsigned long long)sb[0][tap]
                    | ((unsigned long long)sb[1][tap] << 32);
            g_cb.w[set][oc][tap] = wd[tap];
            pc[tap] = (unsigned long long)__popcll(wd[tap]);
        }
        g_cb.w[set][oc][9] = 0ull;

        unsigned long long tab = 0;
        tab |= (pc[0] + pc[1] + pc[2]);         // row0
        tab |= (pc[6] + pc[7] + pc[8]) << 8;    // row2
        tab |= (pc[0] + pc[3] + pc[6]) << 16;   // col0
        tab |= (pc[2] + pc[5] + pc[8]) << 24;   // col2
        tab |= pc[0] << 32;                     // corners
        tab |= pc[2] << 40;
        tab |= pc[6] << 48;
        tab |= pc[8] << 56;
        g_cb.tab[set][oc] = tab;

        if (set == 0) {
            g_cb.par[0][oc] = make_float4(ALPHA * scale, b12[oc], a1[oc], b13[oc]);
            g_cb.k1[oc] = b21[oc];
        } else {
            g_cb.par[1][oc] = make_float4(ALPHA * scale, b22[oc], a2[oc], b23[oc]);
        }
    }
}

// ---------------------------------------------------------------------------
// K1: pack1 — 4 pixels/thread, LDG.128 reads + STG.128 writes.
// bits1[pix] = bitpack over c of (x + b11[c] >= 0).
// ---------------------------------------------------------------------------
__global__ void pack1_kernel(const float* __restrict__ x,
                             const float* __restrict__ b11)
{
    __shared__ float sb[64];
    if (threadIdx.x < 64) sb[threadIdx.x] = b11[threadIdx.x];
    __syncthreads();

    int t = blockIdx.x * blockDim.x + threadIdx.x;
    if (t >= BHW / 4) return;
    int b = t / (HW / 4);
    int hw = (t - b * (HW / 4)) * 4;
    const float4* xp = (const float4*)(x + (size_t)b * Cn * HW + hw);

    unsigned long long w0 = 0, w1 = 0, w2 = 0, w3v = 0;
    #pragma unroll 8
    for (int c = 0; c < 64; c++) {
        float4 v = __ldg(&xp[c * (HW / 4)]);
        float bc = sb[c];
        w0  |= (unsigned long long)(v.x + bc >= 0.f) << c;
        w1  |= (unsigned long long)(v.y + bc >= 0.f) << c;
        w2  |= (unsigned long long)(v.z + bc >= 0.f) << c;
        w3v |= (unsigned long long)(v.w + bc >= 0.f) << c;
    }
    ulonglong2* dst = (ulonglong2*)(g_bits1 + (size_t)b * HW + hw);
    dst[0] = make_ulonglong2(w0, w1);
    dst[1] = make_ulonglong2(w2, w3v);
}

// ---------------------------------------------------------------------------
// Per-pixel conv body. EDGE=false: branch-free (all 9 neighbors valid,
// basei=576, no correction). EDGE=true: OOB taps read as 0, over-count
// corrected via per-oc byte table (R4-validated).
// ---------------------------------------------------------------------------
template <int STAGE, bool EDGE>
__device__ __forceinline__ void conv_pixel(int img, int y, int x,
                                           const float* __restrict__ resid,
                                           float* __restrict__ outp)
{
    const int hw = y * Wn + x;
    const unsigned long long* bp =
        ((STAGE == 1) ? g_bits1 : g_bits2) + (size_t)img * HW;

    unsigned long long nb[9];
    int basei;
    int t0 = 0, bo = 0, lf = 0, rt = 0;

    if (!EDGE) {
        #pragma unroll
        for (int rr = 0; rr < 3; rr++) {
            int rb = hw + (rr - 1) * Wn;
            nb[rr * 3 + 0] = bp[rb - 1];
            nb[rr * 3 + 1] = bp[rb];
            nb[rr * 3 + 2] = bp[rb + 1];
        }
        basei = 576;
    } else {
        t0 = (y == 0); bo = (y == Hn - 1); lf = (x == 0); rt = (x == Wn - 1);
        #pragma unroll
        for (int rr = 0; rr < 3; rr++) {
            bool rok = (rr == 0) ? !t0 : (rr == 2) ? !bo : true;
            int rb = hw + (rr - 1) * Wn;
            nb[rr * 3 + 0] = (rok && !lf) ? bp[rb - 1] : 0ull;
            nb[rr * 3 + 1] =  rok         ? bp[rb]     : 0ull;
            nb[rr * 3 + 2] = (rok && !rt) ? bp[rb + 1] : 0ull;
        }
        basei = 64 * (3 - t0 - bo) * (3 - lf - rt);
    }

    const float* rp = resid + (size_t)img * Cn * HW + hw;
    float*       op = outp  + (size_t)img * Cn * HW + hw;

    unsigned long long pk = 0ull;

    #pragma unroll
    for (int c8 = 0; c8 < 8; c8++) {
        const int oc0 = c8 * 8;

        float r[8];
        #pragma unroll
        for (int j = 0; j < 8; j++)
            r[j] = rp[(oc0 + j) * HW];

        #pragma unroll
        for (int j = 0; j < 8; j++) {
            const int oc = oc0 + j;
            const unsigned long long* wp = c_cb.w[STAGE - 1][oc];

            int a = 0;
            #pragma unroll
            for (int t = 0; t < 9; t++)
                a += __popcll(nb[t] ^ wp[t]);

            int d;
            if (!EDGE) {
                d = basei - 2 * a;
            } else {
                unsigned long long s = c_cb.tab[STAGE - 1][oc];
                int WR0 = (int)(s & 0xFF),         WR2 = (int)((s >> 8)  & 0xFF);
                int WC0 = (int)((s >> 16) & 0xFF), WC2 = (int)((s >> 24) & 0xFF);
                int p00 = (int)((s >> 32) & 0xFF), p02 = (int)((s >> 40) & 0xFF);
                int p20 = (int)((s >> 48) & 0xFF), p22 = (int)((s >> 56) & 0xFF);
                int corr = t0 * WR0 + bo * WR2 + lf * WC0 + rt * WC2
                         - (t0 & lf) * p00 - (t0 & rt) * p02
                         - (bo & lf) * p20 - (bo & rt) * p22;
                d = basei - 2 * (a - corr);
            }

            float4 P = c_cb.par[STAGE - 1][oc];   // {ALPHA*scale, bA, aP, bB}
            float o = fmaf(P.x, (float)d, r[j]);
            float u = o + P.y;
            o = (u >= 0.f ? u : P.z * u) + P.w;
            op[oc * HW] = o;
            if (STAGE == 1)
                pk |= (unsigned long long)(o + c_cb.k1[oc] >= 0.f) << oc;
        }
    }
    if (STAGE == 1) g_bits2[(size_t)img * HW + hw] = pk;
}

// ---------------------------------------------------------------------------
// Conv kernel: CTAs [0, NI_CTAS) handle interior pixels (branch-free path),
// CTAs [NI_CTAS, NI_CTAS+NB_CTAS) handle the 444-px boundary ring.
// ---------------------------------------------------------------------------
template <int STAGE>
__global__ void __launch_bounds__(256, 4)
conv_kernel(const float* __restrict__ resid, float* __restrict__ outp)
{
    const int cta = blockIdx.x;
    if (cta < NI_CTAS) {
        int idx = cta * 256 + threadIdx.x;
        if (idx >= NI_TOT) return;
        int img = idx / NI_IMG;
        int rem = idx - img * NI_IMG;
        int yy = rem / 110;
        int xx = rem - yy * 110;
        conv_pixel<STAGE, false>(img, yy + 1, xx + 1, resid, outp);
    } else {
        int idx = (cta - NI_CTAS) * 256 + threadIdx.x;
        if (idx >= NB_TOT) return;
        int img = idx / NB_IMG;
        int k   = idx - img * NB_IMG;
        int y, x;
        if (k < 112)      { y = 0;           x = k;       }
        else if (k < 224) { y = 111;         x = k - 112; }
        else if (k < 334) { y = k - 224 + 1; x = 0;       }
        else              { y = k - 334 + 1; x = 111;     }
        conv_pixel<STAGE, true>(img, y, x, resid, outp);
    }
}

// ---------------------------------------------------------------------------
extern "C" void kernel_launch(void* const* d_in, const int* in_sizes, int n_in,
                              void* d_out, int out_size)
{
    const float* x   = (const float*)d_in[0];
    const float* w3  = (const float*)d_in[1];
    const float* wpw = (const float*)d_in[2];
    const float* b11 = (const float*)d_in[3];
    const float* b12 = (const float*)d_in[4];
    const float* b13 = (const float*)d_in[5];
    const float* b21 = (const float*)d_in[6];
    const float* b22 = (const float*)d_in[7];
    const float* b23 = (const float*)d_in[8];
    const float* a1  = (const float*)d_in[9];
    const float* a2  = (const float*)d_in[10];
    float* out = (float*)d_out;

    void *p_stage = nullptr, *p_const = nullptr, *p_out1 = nullptr;
    cudaGetSymbolAddress(&p_stage, g_cb);
    cudaGetSymbolAddress(&p_const, c_cb);
    cudaGetSymbolAddress(&p_out1, g_out1);

    prep_weights<<<128, 64>>>(w3, wpw, b12, a1, b13, b22, a2, b23, b21);
    cudaMemcpyAsync(p_const, p_stage, sizeof(CParams), cudaMemcpyDeviceToDevice);
    pack1_kernel<<<(BHW / 4 + 255) / 256, 256>>>(x, b11);
    conv_kernel<1><<<NI_CTAS + NB_CTAS, 256>>>(x, (float*)p_out1);
    conv_kernel<2><<<NI_CTAS + NB_CTAS, 256>>>((const float*)p_out1, out);
}

// round 13
// speedup vs baseline: 3.8195x; 1.0439x over previous
#include <cuda_runtime.h>
#include <cstdint>

// Problem constants
#define Bn 32
#define Cn 64
#define Hn 112
#define Wn 112
static constexpr int HW    = Hn * Wn;        // 12544
static constexpr int BHW   = Bn * HW;        // 401408
static constexpr int TOTAL = Bn * Cn * HW;   // 25690112
static constexpr float ALPHA = 0.25f;

// Interior quads: y in [1,110], x0 = 4 + 4q, q in [0,26)  (x 4..107)
static constexpr int NQ_IMG  = 110 * 26;     // 2860 quads / image
static constexpr int NQ_TOT  = Bn * NQ_IMG;  // 91520
static constexpr int NI_CTAS = NQ_TOT / 128; // 715 (exact)
// Boundary: rows 0,111 (224) + cols 0,111 (220) + cols 1,2,3,108,109,110 (660)
static constexpr int NB_IMG  = 1104;
static constexpr int NB_TOT  = Bn * NB_IMG;  // 35328
static constexpr int NB_CTAS = NB_TOT / 128; // 276 (exact)

// Scratch (no cudaMalloc allowed)
__device__ unsigned long long g_bits1[BHW];
__device__ unsigned long long g_bits2[BHW];
__device__ float g_out1[TOTAL];              // ~103 MB .bss

struct CParams {
    unsigned long long w[2][Cn][10];   // packed sign words (tap 0..8) + pad
    unsigned long long tab[2][Cn];     // byte-packed boundary popc corrections
    float4 par[2][Cn];                 // interior: {-2*a*s, bA+576*a*s, aP, bB}
    float4 parB[2][Cn];                // boundary: {a*s, bA, aP, bB}
    float  k1[Cn];                     // b21 (stage-1 repack bias)
};
__device__   CParams g_cb;   // staging (written by prep kernel)
__constant__ CParams c_cb;   // read by conv kernels

// ---------------------------------------------------------------------------
// K0: PARALLEL weight prep. grid = 128 blocks (set*64+oc), block = 64 (ic).
// ---------------------------------------------------------------------------
__global__ void prep_weights(const float* __restrict__ w3,
                             const float* __restrict__ wpw,
                             const float* __restrict__ b12,
                             const float* __restrict__ a1,
                             const float* __restrict__ b13,
                             const float* __restrict__ b22,
                             const float* __restrict__ a2,
                             const float* __restrict__ b23,
                             const float* __restrict__ b21)
{
    const int set = blockIdx.x >> 6;
    const int oc  = blockIdx.x & 63;
    const int ic  = threadIdx.x;          // 0..63
    const int lane = ic & 31, wrp = ic >> 5;
    const float* w = set ? wpw : w3;

    __shared__ float ssum[64];
    __shared__ unsigned sb[2][9];

    float s = 0.f;
    unsigned mybits = 0;
    #pragma unroll
    for (int tap = 0; tap < 9; tap++) {
        float v = w[(oc * 64 + ic) * 9 + tap];
        s += fabsf(v);
        mybits |= (v >= 0.f) ? (1u << tap) : 0u;
    }
    #pragma unroll
    for (int tap = 0; tap < 9; tap++) {
        unsigned bal = __ballot_sync(0xFFFFFFFFu, (mybits >> tap) & 1u);
        if (lane == 0) sb[wrp][tap] = bal;
    }
    ssum[ic] = s;
    __syncthreads();

    if (ic == 0) {
        float t = 0.f;
        #pragma unroll
        for (int i = 0; i < 64; i++) t += ssum[i];
        float as = t * (1.f / 576.f) * ALPHA;     // ALPHA * scale

        unsigned long long wd[9], pc[9];
        #pragma unroll
        for (int tap = 0; tap < 9; tap++) {
            wd[tap] = (unsigned long long)sb[0][tap]
                    | ((unsigned long long)sb[1][tap] << 32);
            g_cb.w[set][oc][tap] = wd[tap];
            pc[tap] = (unsigned long long)__popcll(wd[tap]);
        }
        g_cb.w[set][oc][9] = 0ull;

        unsigned long long tab = 0;
        tab |= (pc[0] + pc[1] + pc[2]);         // row0
        tab |= (pc[6] + pc[7] + pc[8]) << 8;    // row2
        tab |= (pc[0] + pc[3] + pc[6]) << 16;   // col0
        tab |= (pc[2] + pc[5] + pc[8]) << 24;   // col2
        tab |= pc[0] << 32;                     // corners
        tab |= pc[2] << 40;
        tab |= pc[6] << 48;
        tab |= pc[8] << 56;
        g_cb.tab[set][oc] = tab;

        if (set == 0) {
            g_cb.par[0][oc]  = make_float4(-2.f * as, b12[oc] + 576.f * as, a1[oc], b13[oc]);
            g_cb.parB[0][oc] = make_float4(as, b12[oc], a1[oc], b13[oc]);
            g_cb.k1[oc] = b21[oc];
        } else {
            g_cb.par[1][oc]  = make_float4(-2.f * as, b22[oc] + 576.f * as, a2[oc], b23[oc]);
            g_cb.parB[1][oc] = make_float4(as, b22[oc], a2[oc], b23[oc]);
        }
    }
}

// ---------------------------------------------------------------------------
// K1: pack1 — 4 pixels/thread, LDG.128 reads + STG.128 writes.
// ---------------------------------------------------------------------------
__global__ void pack1_kernel(const float* __restrict__ x,
                             const float* __restrict__ b11)
{
    __shared__ float sb[64];
    if (threadIdx.x < 64) sb[threadIdx.x] = b11[threadIdx.x];
    __syncthreads();

    int t = blockIdx.x * blockDim.x + threadIdx.x;
    if (t >= BHW / 4) return;
    int b = t / (HW / 4);
    int hw = (t - b * (HW / 4)) * 4;
    const float4* xp = (const float4*)(x + (size_t)b * Cn * HW + hw);

    unsigned long long w0 = 0, w1 = 0, w2 = 0, w3v = 0;
    #pragma unroll 8
    for (int c = 0; c < 64; c++) {
        float4 v = __ldg(&xp[c * (HW / 4)]);
        float bc = sb[c];
        w0  |= (unsigned long long)(v.x + bc >= 0.f) << c;
        w1  |= (unsigned long long)(v.y + bc >= 0.f) << c;
        w2  |= (unsigned long long)(v.z + bc >= 0.f) << c;
        w3v |= (unsigned long long)(v.w + bc >= 0.f) << c;
    }
    ulonglong2* dst = (ulonglong2*)(g_bits1 + (size_t)b * HW + hw);
    dst[0] = make_ulonglong2(w0, w1);
    dst[1] = make_ulonglong2(w2, w3v);
}

// ---------------------------------------------------------------------------
// Interior quad path: 4 horizontally-adjacent pixels per thread, all taps
// valid, branch-free, float4 residual/store, folded constants.
// ---------------------------------------------------------------------------
template <int STAGE>
__device__ __forceinline__ void conv_quad(int idx,
                                          const float* __restrict__ resid,
                                          float* __restrict__ outp)
{
    const int img = idx / NQ_IMG;
    const int rem = idx - img * NQ_IMG;
    const int y   = 1 + rem / 26;
    const int q   = rem - (rem / 26) * 26;
    const int x0  = 4 + q * 4;
    const int hw0 = y * Wn + x0;

    const unsigned long long* bp =
        ((STAGE == 1) ? g_bits1 : g_bits2) + (size_t)img * HW;

    // 3 rows x 6 words neighborhood (x0-1 .. x0+4), all in-bounds
    unsigned long long nb[3][6];
    #pragma unroll
    for (int rr = 0; rr < 3; rr++) {
        const unsigned long long* rowp = bp + hw0 + (rr - 1) * Wn - 1;
        #pragma unroll
        for (int k = 0; k < 6; k++) nb[rr][k] = rowp[k];
    }

    const float* rp = resid + (size_t)img * Cn * HW + hw0;
    float*       op = outp  + (size_t)img * Cn * HW + hw0;

    unsigned long long pk0 = 0, pk1 = 0, pk2 = 0, pk3 = 0;

    #pragma unroll 1
    for (int c4 = 0; c4 < 16; c4++) {
        // batched residual loads (4 oc x float4)
        float4 rv[4];
        #pragma unroll
        for (int j = 0; j < 4; j++)
            rv[j] = *(const float4*)(rp + (c4 * 4 + j) * HW);

        #pragma unroll
        for (int j = 0; j < 4; j++) {
            const int oc = c4 * 4 + j;
            const unsigned long long* wp = c_cb.w[STAGE - 1][oc];

            int a0 = 0, a1 = 0, a2 = 0, a3 = 0;
            #pragma unroll
            for (int rr = 0; rr < 3; rr++) {
                #pragma unroll
                for (int cc = 0; cc < 3; cc++) {
                    unsigned long long wt = wp[rr * 3 + cc];
                    a0 += __popcll(nb[rr][cc]     ^ wt);
                    a1 += __popcll(nb[rr][cc + 1] ^ wt);
                    a2 += __popcll(nb[rr][cc + 2] ^ wt);
                    a3 += __popcll(nb[rr][cc + 3] ^ wt);
                }
            }

            float4 P = c_cb.par[STAGE - 1][oc];  // {-2as, bA+576as, aP, bB}
            float u0 = fmaf(P.x, (float)a0, rv[j].x) + P.y;
            float u1 = fmaf(P.x, (float)a1, rv[j].y) + P.y;
            float u2 = fmaf(P.x, (float)a2, rv[j].z) + P.y;
            float u3 = fmaf(P.x, (float)a3, rv[j].w) + P.y;
            float4 o;
            o.x = (u0 >= 0.f ? u0 : P.z * u0) + P.w;
            o.y = (u1 >= 0.f ? u1 : P.z * u1) + P.w;
            o.z = (u2 >= 0.f ? u2 : P.z * u2) + P.w;
            o.w = (u3 >= 0.f ? u3 : P.z * u3) + P.w;
            *(float4*)(op + oc * HW) = o;

            if (STAGE == 1) {
                float k = c_cb.k1[oc];
                pk0 |= (unsigned long long)(o.x + k >= 0.f) << oc;
                pk1 |= (unsigned long long)(o.y + k >= 0.f) << oc;
                pk2 |= (unsigned long long)(o.z + k >= 0.f) << oc;
                pk3 |= (unsigned long long)(o.w + k >= 0.f) << oc;
            }
        }
    }
    if (STAGE == 1) {
        ulonglong2* dst = (ulonglong2*)(g_bits2 + (size_t)img * HW + hw0);
        dst[0] = make_ulonglong2(pk0, pk1);
        dst[1] = make_ulonglong2(pk2, pk3);
    }
}

// ---------------------------------------------------------------------------
// Boundary path: general masked conv (1 px/thread), table-corrected.
// ---------------------------------------------------------------------------
template <int STAGE>
__device__ __forceinline__ void conv_edge(int img, int y, int x,
                                          const float* __restrict__ resid,
                                          float* __restrict__ outp)
{
    const int hw = y * Wn + x;
    const unsigned long long* bp =
        ((STAGE == 1) ? g_bits1 : g_bits2) + (size_t)img * HW;

    const int t0 = (y == 0), bo = (y == Hn - 1), lf = (x == 0), rt = (x == Wn - 1);

    unsigned long long nb[9];
    #pragma unroll
    for (int rr = 0; rr < 3; rr++) {
        bool rok = (rr == 0) ? !t0 : (rr == 2) ? !bo : true;
        int rb = hw + (rr - 1) * Wn;
        nb[rr * 3 + 0] = (rok && !lf) ? bp[rb - 1] : 0ull;
        nb[rr * 3 + 1] =  rok         ? bp[rb]     : 0ull;
        nb[rr * 3 + 2] = (rok && !rt) ? bp[rb + 1] : 0ull;
    }
    const int basei = 64 * (3 - t0 - bo) * (3 - lf - rt);

    const float* rp = resid + (size_t)img * Cn * HW + hw;
    float*       op = outp  + (size_t)img * Cn * HW + hw;

    unsigned long long pk = 0ull;

    #pragma unroll 1
    for (int c8 = 0; c8 < 8; c8++) {
        const int oc0 = c8 * 8;
        float r[8];
        #pragma unroll
        for (int j = 0; j < 8; j++) r[j] = rp[(oc0 + j) * HW];

        #pragma unroll
        for (int j = 0; j < 8; j++) {
            const int oc = oc0 + j;
            const unsigned long long* wp = c_cb.w[STAGE - 1][oc];
            int a = 0;
            #pragma unroll
            for (int t = 0; t < 9; t++)
                a += __popcll(nb[t] ^ wp[t]);

            unsigned long long s = c_cb.tab[STAGE - 1][oc];
            int WR0 = (int)(s & 0xFF),         WR2 = (int)((s >> 8)  & 0xFF);
            int WC0 = (int)((s >> 16) & 0xFF), WC2 = (int)((s >> 24) & 0xFF);
            int p00 = (int)((s >> 32) & 0xFF), p02 = (int)((s >> 40) & 0xFF);
            int p20 = (int)((s >> 48) & 0xFF), p22 = (int)((s >> 56) & 0xFF);
            int corr = t0 * WR0 + bo * WR2 + lf * WC0 + rt * WC2
                     - (t0 & lf) * p00 - (t0 & rt) * p02
                     - (bo & lf) * p20 - (bo & rt) * p22;
            int d = basei - 2 * (a - corr);

            float4 P = c_cb.parB[STAGE - 1][oc];   // {as, bA, aP, bB}
            float o = fmaf(P.x, (float)d, r[j]);
            float u = o + P.y;
            o = (u >= 0.f ? u : P.z * u) + P.w;
            op[oc * HW] = o;
            if (STAGE == 1)
                pk |= (unsigned long long)(o + c_cb.k1[oc] >= 0.f) << oc;
        }
    }
    if (STAGE == 1) g_bits2[(size_t)img * HW + hw] = pk;
}

// ---------------------------------------------------------------------------
template <int STAGE>
__global__ void __launch_bounds__(128, 6)
conv_kernel(const float* __restrict__ resid, float* __restrict__ outp)
{
    const int cta = blockIdx.x;
    if (cta < NI_CTAS) {
        int idx = cta * 128 + threadIdx.x;        // < NQ_TOT (exact multiple)
        conv_quad<STAGE>(idx, resid, outp);
    } else {
        int idx = (cta - NI_CTAS) * 128 + threadIdx.x;   // < NB_TOT (exact)
        int img = idx / NB_IMG;
        int k   = idx - img * NB_IMG;
        int y, x;
        if (k < 112)      { y = 0;            x = k;        }
        else if (k < 224) { y = 111;          x = k - 112;  }
        else if (k < 334) { y = 1 + k - 224;  x = 0;        }
        else if (k < 444) { y = 1 + k - 334;  x = 111;      }
        else {
            int m = k - 444;
            int col = m / 110;
            y = 1 + (m - col * 110);
            x = (col < 3) ? (1 + col) : (105 + col);   // 1,2,3,108,109,110
        }
        conv_edge<STAGE>(img, y, x, resid, outp);
    }
}

// ---------------------------------------------------------------------------
extern "C" void kernel_launch(void* const* d_in, const int* in_sizes, int n_in,
                              void* d_out, int out_size)
{
    const float* x   = (const float*)d_in[0];
    const float* w3  = (const float*)d_in[1];
    const float* wpw = (const float*)d_in[2];
    const float* b11 = (const float*)d_in[3];
    const float* b12 = (const float*)d_in[4];
    const float* b13 = (const float*)d_in[5];
    const float* b21 = (const float*)d_in[6];
    const float* b22 = (const float*)d_in[7];
    const float* b23 = (const float*)d_in[8];
    const float* a1  = (const float*)d_in[9];
    const float* a2  = (const float*)d_in[10];
    float* out = (float*)d_out;

    void *p_stage = nullptr, *p_const = nullptr, *p_out1 = nullptr;
    cudaGetSymbolAddress(&p_stage, g_cb);
    cudaGetSymbolAddress(&p_const, c_cb);
    cudaGetSymbolAddress(&p_out1, g_out1);

    prep_weights<<<128, 64>>>(w3, wpw, b12, a1, b13, b22, a2, b23, b21);
    cudaMemcpyAsync(p_const, p_stage, sizeof(CParams), cudaMemcpyDeviceToDevice);
    pack1_kernel<<<(BHW / 4 + 255) / 256, 256>>>(x, b11);
    conv_kernel<1><<<NI_CTAS + NB_CTAS, 128>>>(x, (float*)p_out1);
    conv_kernel<2><<<NI_CTAS + NB_CTAS, 128>>>((const float*)p_out1, out);
}

// round 17
// speedup vs baseline: 4.2958x; 1.1247x over previous
#include <cuda_runtime.h>
#include <cstdint>

// Problem constants
#define Bn 32
#define Cn 64
#define Hn 112
#define Wn 112
static constexpr int HW    = Hn * Wn;        // 12544
static constexpr int BHW   = Bn * HW;        // 401408
static constexpr int TOTAL = Bn * Cn * HW;   // 25690112
static constexpr float ALPHA = 0.25f;

// Interior pairs: y in [1,110], x0 = 2 + 2q, q in [0,54)  (x 2..109)
static constexpr int NP_IMG  = 110 * 54;     // 5940 pairs / image
static constexpr int NP_TOT  = Bn * NP_IMG;  // 190080
static constexpr int NP_CTAS = (NP_TOT + 255) / 256;   // 743
// Boundary: rows 0,111 (224) + cols {0,1,110,111} x y[1,110] (440) = 664
static constexpr int NB_IMG  = 664;
static constexpr int NB_TOT  = Bn * NB_IMG;  // 21248
static constexpr int NB_CTAS = NB_TOT / 256; // 83 (exact)

// Scratch (no cudaMalloc allowed)
__device__ unsigned long long g_bits1[BHW];
__device__ unsigned long long g_bits2[BHW];
__device__ float g_out1[TOTAL];              // ~103 MB .bss

struct CParams {
    unsigned long long w[2][Cn][10];   // packed sign words (tap 0..8) + pad
    unsigned long long tab[2][Cn];     // byte-packed boundary popc corrections
    float4 par[2][Cn];                 // interior: {-2*a*s, bA+576*a*s, aP, bB}
    float4 parB[2][Cn];                // boundary: {a*s, bA, aP, bB}
    float  k1[Cn];                     // b21 (stage-1 repack bias)
};
__device__   CParams g_cb;   // staging (written by prep kernel)
__constant__ CParams c_cb;   // read by conv kernels

// Exact int->float for a in [0, 2^23): IADD + FADD instead of I2F.
__device__ __forceinline__ float fast_i2f(int a) {
    return __int_as_float(a + 0x4B000000) - 8388608.0f;
}

// ---------------------------------------------------------------------------
// K0: PARALLEL weight prep. grid = 128 blocks (set*64+oc), block = 64 (ic).
// ---------------------------------------------------------------------------
__global__ void prep_weights(const float* __restrict__ w3,
                             const float* __restrict__ wpw,
                             const float* __restrict__ b12,
                             const float* __restrict__ a1,
                             const float* __restrict__ b13,
                             const float* __restrict__ b22,
                             const float* __restrict__ a2,
                             const float* __restrict__ b23,
                             const float* __restrict__ b21)
{
    const int set = blockIdx.x >> 6;
    const int oc  = blockIdx.x & 63;
    const int ic  = threadIdx.x;          // 0..63
    const int lane = ic & 31, wrp = ic >> 5;
    const float* w = set ? wpw : w3;

    __shared__ float ssum[64];
    __shared__ unsigned sb[2][9];

    float s = 0.f;
    unsigned mybits = 0;
    #pragma unroll
    for (int tap = 0; tap < 9; tap++) {
        float v = w[(oc * 64 + ic) * 9 + tap];
        s += fabsf(v);
        mybits |= (v >= 0.f) ? (1u << tap) : 0u;
    }
    #pragma unroll
    for (int tap = 0; tap < 9; tap++) {
        unsigned bal = __ballot_sync(0xFFFFFFFFu, (mybits >> tap) & 1u);
        if (lane == 0) sb[wrp][tap] = bal;
    }
    ssum[ic] = s;
    __syncthreads();

    if (ic == 0) {
        float t = 0.f;
        #pragma unroll
        for (int i = 0; i < 64; i++) t += ssum[i];
        float as = t * (1.f / 576.f) * ALPHA;     // ALPHA * scale

        unsigned long long wd[9], pc[9];
        #pragma unroll
        for (int tap = 0; tap < 9; tap++) {
            wd[tap] = (unsigned long long)sb[0][tap]
                    | ((unsigned long long)sb[1][tap] << 32);
            g_cb.w[set][oc][tap] = wd[tap];
            pc[tap] = (unsigned long long)__popcll(wd[tap]);
        }
        g_cb.w[set][oc][9] = 0ull;

        unsigned long long tab = 0;
        tab |= (pc[0] + pc[1] + pc[2]);         // row0
        tab |= (pc[6] + pc[7] + pc[8]) << 8;    // row2
        tab |= (pc[0] + pc[3] + pc[6]) << 16;   // col0
        tab |= (pc[2] + pc[5] + pc[8]) << 24;   // col2
        tab |= pc[0] << 32;                     // corners
        tab |= pc[2] << 40;
        tab |= pc[6] << 48;
        tab |= pc[8] << 56;
        g_cb.tab[set][oc] = tab;

        if (set == 0) {
            g_cb.par[0][oc]  = make_float4(-2.f * as, b12[oc] + 576.f * as, a1[oc], b13[oc]);
            g_cb.parB[0][oc] = make_float4(as, b12[oc], a1[oc], b13[oc]);
            g_cb.k1[oc] = b21[oc];
        } else {
            g_cb.par[1][oc]  = make_float4(-2.f * as, b22[oc] + 576.f * as, a2[oc], b23[oc]);
            g_cb.parB[1][oc] = make_float4(as, b22[oc], a2[oc], b23[oc]);
        }
    }
}

// ---------------------------------------------------------------------------
// K1: pack1 — 4 pixels/thread, LDG.128 reads + STG.128 writes.
// ---------------------------------------------------------------------------
__global__ void pack1_kernel(const float* __restrict__ x,
                             const float* __restrict__ b11)
{
    __shared__ float sb[64];
    if (threadIdx.x < 64) sb[threadIdx.x] = b11[threadIdx.x];
    __syncthreads();

    int t = blockIdx.x * blockDim.x + threadIdx.x;
    if (t >= BHW / 4) return;
    int b = t / (HW / 4);
    int hw = (t - b * (HW / 4)) * 4;
    const float4* xp = (const float4*)(x + (size_t)b * Cn * HW + hw);

    unsigned long long w0 = 0, w1 = 0, w2 = 0, w3v = 0;
    #pragma unroll 8
    for (int c = 0; c < 64; c++) {
        float4 v = __ldg(&xp[c * (HW / 4)]);
        float bc = sb[c];
        w0  |= (unsigned long long)(v.x + bc >= 0.f) << c;
        w1  |= (unsigned long long)(v.y + bc >= 0.f) << c;
        w2  |= (unsigned long long)(v.z + bc >= 0.f) << c;
        w3v |= (unsigned long long)(v.w + bc >= 0.f) << c;
    }
    ulonglong2* dst = (ulonglong2*)(g_bits1 + (size_t)b * HW + hw);
    dst[0] = make_ulonglong2(w0, w1);
    dst[1] = make_ulonglong2(w2, w3v);
}

// ---------------------------------------------------------------------------
// Interior pair path: 2 horizontally-adjacent pixels/thread (x0 even), all
// taps valid, branch-free; float2 residual/store; folded constants; no I2F.
// ---------------------------------------------------------------------------
template <int STAGE>
__device__ __forceinline__ void conv_pair(int idx,
                                          const float* __restrict__ resid,
                                          float* __restrict__ outp)
{
    const int img = idx / NP_IMG;
    const int rem = idx - img * NP_IMG;
    const int y   = 1 + rem / 54;
    const int q   = rem - (rem / 54) * 54;
    const int x0  = 2 + q * 2;
    const int hw0 = y * Wn + x0;            // even -> 8B/16B alignment holds

    const unsigned long long* bp =
        ((STAGE == 1) ? g_bits1 : g_bits2) + (size_t)img * HW;

    // 3 rows x 4 words neighborhood (x0-1 .. x0+2), all in-bounds
    unsigned long long nb[3][4];
    #pragma unroll
    for (int rr = 0; rr < 3; rr++) {
        const unsigned long long* rowp = bp + hw0 + (rr - 1) * Wn - 1;
        #pragma unroll
        for (int k = 0; k < 4; k++) nb[rr][k] = rowp[k];
    }

    const float* rp = resid + (size_t)img * Cn * HW + hw0;
    float*       op = outp  + (size_t)img * Cn * HW + hw0;

    unsigned long long pk0 = 0, pk1 = 0;

    #pragma unroll 1
    for (int c8 = 0; c8 < 8; c8++) {
        // batched residual loads (8 oc x float2, MLP=8)
        float2 rv[8];
        #pragma unroll
        for (int j = 0; j < 8; j++)
            rv[j] = *(const float2*)(rp + (c8 * 8 + j) * HW);

        #pragma unroll
        for (int j = 0; j < 8; j++) {
            const int oc = c8 * 8 + j;
            const unsigned long long* wp = c_cb.w[STAGE - 1][oc];

            int a0 = 0, a1 = 0;
            #pragma unroll
            for (int rr = 0; rr < 3; rr++) {
                #pragma unroll
                for (int cc = 0; cc < 3; cc++) {
                    unsigned long long wt = wp[rr * 3 + cc];
                    a0 += __popcll(nb[rr][cc]     ^ wt);
                    a1 += __popcll(nb[rr][cc + 1] ^ wt);
                }
            }
            float f0 = fast_i2f(a0);
            float f1 = fast_i2f(a1);

            float4 P = c_cb.par[STAGE - 1][oc];  // {-2as, bA+576as, aP, bB}
            float u0 = fmaf(P.x, f0, rv[j].x) + P.y;
            float u1 = fmaf(P.x, f1, rv[j].y) + P.y;
            float2 o;
            o.x = (u0 >= 0.f ? u0 : P.z * u0) + P.w;
            o.y = (u1 >= 0.f ? u1 : P.z * u1) + P.w;
            *(float2*)(op + oc * HW) = o;

            if (STAGE == 1) {
                float k = c_cb.k1[oc];
                pk0 |= (unsigned long long)(o.x + k >= 0.f) << oc;
                pk1 |= (unsigned long long)(o.y + k >= 0.f) << oc;
            }
        }
    }
    if (STAGE == 1) {
        *(ulonglong2*)(g_bits2 + (size_t)img * HW + hw0) =
            make_ulonglong2(pk0, pk1);
    }
}

// ---------------------------------------------------------------------------
// Boundary path: general masked conv (1 px/thread), table-corrected.
// ---------------------------------------------------------------------------
template <int STAGE>
__device__ __forceinline__ void conv_edge(int img, int y, int x,
                                          const float* __restrict__ resid,
                                          float* __restrict__ outp)
{
    const int hw = y * Wn + x;
    const unsigned long long* bp =
        ((STAGE == 1) ? g_bits1 : g_bits2) + (size_t)img * HW;

    const int t0 = (y == 0), bo = (y == Hn - 1), lf = (x == 0), rt = (x == Wn - 1);

    unsigned long long nb[9];
    #pragma unroll
    for (int rr = 0; rr < 3; rr++) {
        bool rok = (rr == 0) ? !t0 : (rr == 2) ? !bo : true;
        int rb = hw + (rr - 1) * Wn;
        nb[rr * 3 + 0] = (rok && !lf) ? bp[rb - 1] : 0ull;
        nb[rr * 3 + 1] =  rok         ? bp[rb]     : 0ull;
        nb[rr * 3 + 2] = (rok && !rt) ? bp[rb + 1] : 0ull;
    }
    const int basei = 64 * (3 - t0 - bo) * (3 - lf - rt);

    const float* rp = resid + (size_t)img * Cn * HW + hw;
    float*       op = outp  + (size_t)img * Cn * HW + hw;

    unsigned long long pk = 0ull;

    #pragma unroll 1
    for (int c8 = 0; c8 < 8; c8++) {
        const int oc0 = c8 * 8;
        float r[8];
        #pragma unroll
        for (int j = 0; j < 8; j++) r[j] = rp[(oc0 + j) * HW];

        #pragma unroll
        for (int j = 0; j < 8; j++) {
            const int oc = oc0 + j;
            const unsigned long long* wp = c_cb.w[STAGE - 1][oc];
            int a = 0;
            #pragma unroll
            for (int t = 0; t < 9; t++)
                a += __popcll(nb[t] ^ wp[t]);

            unsigned long long s = c_cb.tab[STAGE - 1][oc];
            int WR0 = (int)(s & 0xFF),         WR2 = (int)((s >> 8)  & 0xFF);
            int WC0 = (int)((s >> 16) & 0xFF), WC2 = (int)((s >> 24) & 0xFF);
            int p00 = (int)((s >> 32) & 0xFF), p02 = (int)((s >> 40) & 0xFF);
            int p20 = (int)((s >> 48) & 0xFF), p22 = (int)((s >> 56) & 0xFF);
            int corr = t0 * WR0 + bo * WR2 + lf * WC0 + rt * WC2
                     - (t0 & lf) * p00 - (t0 & rt) * p02
                     - (bo & lf) * p20 - (bo & rt) * p22;
            int d = basei - 2 * (a - corr);     // in [0, 576]

            float4 P = c_cb.parB[STAGE - 1][oc];   // {as, bA, aP, bB}
            float o = fmaf(P.x, fast_i2f(d), r[j]);
            float u = o + P.y;
            o = (u >= 0.f ? u : P.z * u) + P.w;
            op[oc * HW] = o;
            if (STAGE == 1)
                pk |= (unsigned long long)(o + c_cb.k1[oc] >= 0.f) << oc;
        }
    }
    if (STAGE == 1) g_bits2[(size_t)img * HW + hw] = pk;
}

// ---------------------------------------------------------------------------
template <int STAGE>
__global__ void __launch_bounds__(256, 4)
conv_kernel(const float* __restrict__ resid, float* __restrict__ outp)
{
    const int cta = blockIdx.x;
    if (cta < NP_CTAS) {
        int idx = cta * 256 + threadIdx.x;
        if (idx < NP_TOT)
            conv_pair<STAGE>(idx, resid, outp);
    } else {
        int idx = (cta - NP_CTAS) * 256 + threadIdx.x;   // < NB_TOT (exact)
        int img = idx / NB_IMG;
        int k   = idx - img * NB_IMG;
        int y, x;
        if (k < 112)      { y = 0;    x = k;        }
        else if (k < 224) { y = 111;  x = k - 112;  }
        else if (k < 444) {
            int m = k - 224, col = m / 110;
            x = col;                 // 0 or 1
            y = 1 + (m - col * 110);
        } else {
            int m = k - 444, col = m / 110;
            x = 110 + col;           // 110 or 111
            y = 1 + (m - col * 110);
        }
        conv_edge<STAGE>(img, y, x, resid, outp);
    }
}

// ---------------------------------------------------------------------------
extern "C" void kernel_launch(void* const* d_in, const int* in_sizes, int n_in,
                              void* d_out, int out_size)
{
    const float* x   = (const float*)d_in[0];
    const float* w3  = (const float*)d_in[1];
    const float* wpw = (const float*)d_in[2];
    const float* b11 = (const float*)d_in[3];
    const float* b12 = (const float*)d_in[4];
    const float* b13 = (const float*)d_in[5];
    const float* b21 = (const float*)d_in[6];
    const float* b22 = (const float*)d_in[7];
    const float* b23 = (const float*)d_in[8];
    const float* a1  = (const float*)d_in[9];
    const float* a2  = (const float*)d_in[10];
    float* out = (float*)d_out;

    void *p_stage = nullptr, *p_const = nullptr, *p_out1 = nullptr;
    cudaGetSymbolAddress(&p_stage, g_cb);
    cudaGetSymbolAddress(&p_const, c_cb);
    cudaGetSymbolAddress(&p_out1, g_out1);

    prep_weights<<<128, 64>>>(w3, wpw, b12, a1, b13, b22, a2, b23, b21);
    cudaMemcpyAsync(p_const, p_stage, sizeof(CParams), cudaMemcpyDeviceToDevice);
    pack1_kernel<<<(BHW / 4 + 255) / 256, 256>>>(x, b11);
    conv_kernel<1><<<NP_CTAS + NB_CTAS, 256>>>(x, (float*)p_out1);
    conv_kernel<2><<<NP_CTAS + NB_CTAS, 256>>>((const float*)p_out1, out);
}